// round 10
// baseline (speedup 1.0000x reference)
#include <cuda_runtime.h>
#include <cuda_fp16.h>
#include <math.h>

#define Bb 64
#define Tt 2048
#define Vv 256
#define Uu 256
#define NEGV (-1e30f)

__device__ __half g_dh[(size_t)Bb * Tt * 256]; // d[b,t,i] = logits[b,t,tgt[i]] - logits[b,t,0] (fp16)
__device__ float  g_Cpart[Bb * 256];           // per-8-row blank-logp partials
__device__ float  g_nll[Bb];

__device__ __forceinline__ void cp16(unsigned sa, const float* g) {
    asm volatile("cp.async.cg.shared.global [%0], [%1], 16;\n" :: "r"(sa), "l"(g) : "memory");
}
__device__ __forceinline__ void cp8(unsigned sa, const void* g) {
    asm volatile("cp.async.ca.shared.global [%0], [%1], 8;\n" :: "r"(sa), "l"(g) : "memory");
}
__device__ __forceinline__ void cpcommit() {
    asm volatile("cp.async.commit_group;\n" ::: "memory");
}
template<int N> __device__ __forceinline__ void cpwait() {
    asm volatile("cp.async.wait_group %0;\n" :: "n"(N) : "memory");
}
__device__ __forceinline__ void strel(unsigned a, int v) {
    asm volatile("st.release.cta.shared.b32 [%0], %1;" :: "r"(a), "r"(v) : "memory");
}
__device__ __forceinline__ void spinwait(unsigned a, int need) {
    int v;
    while (true) {
        asm volatile("ld.acquire.cta.shared.b32 %0, [%1];" : "=r"(v) : "r"(a) : "memory");
        if (v >= need) break;
        __nanosleep(64);
    }
}

// ---------------------------------------------------------------------------
// Kernel 1: fused lse + emission-delta gather (fp16 out) + blank-logp partials.
// ---------------------------------------------------------------------------
#define GB_ROWS 64
__global__ void __launch_bounds__(256) gather_kernel(const float* __restrict__ logits,
                                                     const int*  __restrict__ targets,
                                                     const int*  __restrict__ loglen) {
    __shared__ int   sTgt[Uu];
    __shared__ float sRow[8][4][Vv];

    const int b  = blockIdx.y;
    const int c  = blockIdx.x;
    const int L  = loglen[b];
    const int t0 = c * GB_ROWS;
    if (t0 >= L) return;

    const int tid = threadIdx.x, w = tid >> 5, lane = tid & 31;
    sTgt[tid] = targets[b * Uu + tid];
    __syncthreads();

    const int tbase = t0 + w * 8;
    if (tbase >= L) return;
    int nrows = L - tbase; if (nrows > 8) nrows = 8;

    const float* lg    = logits + ((size_t)b * Tt + tbase) * Vv;
    __half*      dOutH = g_dh   + ((size_t)b * Tt + tbase) * 256;

#pragma unroll
    for (int p = 0; p < 3; ++p) {
        if (p < nrows) {
            unsigned sa = (unsigned)__cvta_generic_to_shared(&sRow[w][p][lane * 8]);
            const float* g = lg + (size_t)p * Vv + lane * 8;
            cp16(sa, g);
            cp16(sa + 16, g + 4);
        }
        cpcommit();
    }

    float cb = 0.0f;
    for (int k = 0; k < nrows; ++k) {
        int pf = k + 3;
        if (pf < nrows) {
            unsigned sa = (unsigned)__cvta_generic_to_shared(&sRow[w][pf & 3][lane * 8]);
            const float* g = lg + (size_t)pf * Vv + lane * 8;
            cp16(sa, g);
            cp16(sa + 16, g + 4);
        }
        cpcommit();
        cpwait<3>();
        __syncwarp();

        const float* r = sRow[w][k & 3];
        float4 v0 = *(const float4*)&r[lane * 4];
        float4 v1 = *(const float4*)&r[128 + lane * 4];
        float s = __expf(v0.x) + __expf(v0.y) + __expf(v0.z) + __expf(v0.w)
                + __expf(v1.x) + __expf(v1.y) + __expf(v1.z) + __expf(v1.w);
#pragma unroll
        for (int o = 16; o; o >>= 1) s += __shfl_xor_sync(0xffffffffu, s, o);
        float lse = __logf(s);
        float r0  = __shfl_sync(0xffffffffu, v0.x, 0);
        cb += r0 - lse;

        int4 tg0 = *(const int4*)&sTgt[lane * 8];
        int4 tg1 = *(const int4*)&sTgt[lane * 8 + 4];
        __half2 a0 = __floats2half2_rn(r[tg0.x] - r0, r[tg0.y] - r0);
        __half2 a1 = __floats2half2_rn(r[tg0.z] - r0, r[tg0.w] - r0);
        __half2 a2 = __floats2half2_rn(r[tg1.x] - r0, r[tg1.y] - r0);
        __half2 a3 = __floats2half2_rn(r[tg1.z] - r0, r[tg1.w] - r0);
        uint4 pk;
        pk.x = *(unsigned*)&a0; pk.y = *(unsigned*)&a1;
        pk.z = *(unsigned*)&a2; pk.w = *(unsigned*)&a3;
        *(uint4*)&dOutH[(size_t)k * 256 + lane * 8] = pk;
        __syncwarp();
    }
    if (lane == 0) g_Cpart[b * 256 + (tbase >> 3)] = cb;
}

// ---------------------------------------------------------------------------
// Kernel 2: Viterbi DP. 16 blocks x 8 warps: block handles 4 batches, each
// batch = skewed warp pair (lo pairs 0..127 / hi pairs 128..255+state512).
// wid%4 -> SMSP, so each SMSP co-schedules 2 INDEPENDENT recurrences
// (w and w+4), filling dependency stalls. fp16 ring (64 rows x 256B/warp),
// DPGc=12 issue-before-wait -> 40-step DRAM-latency lead (R9 pipeline).
// ---------------------------------------------------------------------------
#define DPGc 12
#define RROWS 64
#define RINGB (RROWS * 256)                  // ring bytes per warp (16 KB)
__global__ void __launch_bounds__(256, 1) dp_kernel(const int* __restrict__ targets,
                                                    const int* __restrict__ loglen,
                                                    const int* __restrict__ tgtlen) {
    extern __shared__ char sm[];
    // layout: rings[8][16KB] | bnd[4][Tt+8] f32 | sEO[4][520] f32 | dump[4][32] f32 | prog[4]
    char*  ringAll  = sm;
    float* sBndAll  = (float*)(sm + 8 * RINGB);
    float* sEOAll   = sBndAll + 4 * (Tt + 8);
    float* sDumpAll = sEOAll + 4 * 520;
    int*   sProgAll = (int*)(sDumpAll + 4 * 32);

    const int tid  = threadIdx.x;
    const int wid  = tid >> 5;
    const int lane = tid & 31;
    const int q    = wid >> 1;               // batch slot within block (0..3)
    const int role = wid & 1;                // 0 = lo half, 1 = hi half
    const int b    = blockIdx.x * 4 + q;
    const int L    = loglen[b];
    const int Ut   = tgtlen[b];
    const int l4   = lane * 4;
    const int pbase = role * 128 + l4;       // global pair index base
    const __half* __restrict__ emB = g_dh + (size_t)b * Tt * 256 + role * 128;
    char* ring = ringAll + wid * RINGB;
    const unsigned ringB2 = (unsigned)__cvta_generic_to_shared(ring);
    float* sBnd = sBndAll + q * (Tt + 8);
    const unsigned bndB  = (unsigned)__cvta_generic_to_shared(sBnd);
    const unsigned progA = (unsigned)__cvta_generic_to_shared(&sProgAll[q]);

    if (lane == 0 && role == 0) { sProgAll[q] = 0; sBnd[0] = NEGV; }
    __syncthreads();

    float gate[4];
    {
        int prev = (pbase == 0) ? -1 : targets[b * Uu + pbase - 1];
#pragma unroll
        for (int j = 0; j < 4; ++j) {
            int cur = targets[b * Uu + pbase + j];
            gate[j] = (pbase + j >= 1 && cur != prev) ? 0.0f : NEGV;
            prev = cur;
        }
    }

    float E[4], O[4];
#pragma unroll
    for (int j = 0; j < 4; ++j) { E[j] = NEGV; O[j] = NEGV; }
    if (pbase == 0) E[0] = 0.0f;             // alpha_hat seed (lane0 of role0)
    float Eex = NEGV, pO_cur = NEGV;
    const float pOmask = (lane == 0) ? NEGV : 0.0f;

    // branch-free boundary store: lane31 -> bnd slot, others -> private dump
    const unsigned stBase = (lane == 31) ? bndB
                           : (unsigned)__cvta_generic_to_shared(&sDumpAll[q * 32 + lane]);
    const unsigned stStep = (lane == 31) ? 4u : 0u;

#define LDCONV(DST, SLOT)                                                     \
    {                                                                         \
        uint2 v_ = *(const uint2*)(ring + ((SLOT) << 8) + l4 * 2);            \
        float2 f0_ = __half22float2(*(__half2*)&v_.x);                        \
        float2 f1_ = __half22float2(*(__half2*)&v_.y);                        \
        (DST)[0] = f0_.x; (DST)[1] = f0_.y; (DST)[2] = f1_.x; (DST)[3] = f1_.y; \
    }

#define ISSUEG(ROW0)                                                          \
    {                                                                         \
        _Pragma("unroll")                                                     \
        for (int r_ = 0; r_ < 4; ++r_) {                                      \
            int row_ = (ROW0) + r_;                                           \
            if (row_ < L) {                                                   \
                unsigned sa_ = ringB2 + (((unsigned)row_ & (RROWS-1u)) << 8) + (unsigned)l4 * 2u; \
                cp8(sa_, emB + (size_t)row_ * 256 + l4);                      \
            }                                                                 \
        }                                                                     \
        cpcommit();                                                           \
    }

    // prologue: groups 0..11 (rows 0..47; L >= 1024)
#pragma unroll
    for (int g2 = 0; g2 < DPGc; ++g2) ISSUEG(g2 * 4);
    cpwait<DPGc - 2>();                      // rows 0..7 resident

    float buf[4][4];
    LDCONV(buf[0], 0);
    LDCONV(buf[1], 1);

    const int ncfull = L >> 5;
    const int rem32  = L & 31;
    int blk = 0;

#define SUB0(T)                                                               \
    {                                                                         \
        LDCONV(buf[((T) + 2) & 3], (((T) + 2) & (RROWS - 1)));                \
        const float* dv = buf[(T) & 3];                                       \
        float e3 = E[3], o3 = O[3];                                           \
        float O3n = fmaxf(fmaxf(o3, e3), O[2] + gate[3]) + dv[3];             \
        float E3n = fmaxf(e3, O[2]);                                          \
        float nextPO = __shfl_up_sync(0xffffffffu, O3n, 1);                   \
        unsigned dst_ = stBase + (unsigned)((T) + 1) * stStep;                \
        asm volatile("st.shared.b32 [%0], %1;" :: "r"(dst_), "f"(O3n));       \
        float pO = pO_cur;                                                    \
        _Pragma("unroll")                                                     \
        for (int j = 0; j < 3; ++j) {                                         \
            float e = E[j], o = O[j];                                         \
            E[j] = fmaxf(e, pO);                                              \
            O[j] = fmaxf(fmaxf(o, e), pO + gate[j]) + dv[j];                  \
            pO = o;                                                           \
        }                                                                     \
        E[3] = E3n; O[3] = O3n;                                               \
        pO_cur = nextPO + pOmask;                                             \
    }

#define SUB1(T)                                                               \
    {                                                                         \
        LDCONV(buf[((T) + 2) & 3], (((T) + 2) & (RROWS - 1)));                \
        float bn = sBnd[(T) + 1];                                             \
        const float* dv = buf[(T) & 3];                                       \
        float e3 = E[3], o3 = O[3];                                           \
        float O3n = fmaxf(fmaxf(o3, e3), O[2] + gate[3]) + dv[3];             \
        float E3n = fmaxf(e3, O[2]);                                          \
        float nextPO = __shfl_up_sync(0xffffffffu, O3n, 1);                   \
        Eex = fmaxf(Eex, o3);                                                 \
        float pO = pO_cur;                                                    \
        _Pragma("unroll")                                                     \
        for (int j = 0; j < 3; ++j) {                                         \
            float e = E[j], o = O[j];                                         \
            E[j] = fmaxf(e, pO);                                              \
            O[j] = fmaxf(fmaxf(o, e), pO + gate[j]) + dv[j];                  \
            pO = o;                                                           \
        }                                                                     \
        E[3] = E3n; O[3] = O3n;                                               \
        pO_cur = (lane == 0) ? bn : nextPO;                                   \
    }

    if (role == 0) {
        for (int c = 0; c < ncfull; ++c) {
            for (int qq = 0; qq < 8; ++qq, ++blk) {
                ISSUEG((blk + DPGc) * 4);
                cpwait<DPGc - 2>();
                const int t0 = blk * 4;
                SUB0(t0); SUB0(t0 + 1); SUB0(t0 + 2); SUB0(t0 + 3);
            }
            if (lane == 31) strel(progA, c + 1);
        }
        const int rb = rem32 >> 2, rr = rem32 & 3;
        for (int qq = 0; qq < rb; ++qq, ++blk) {
            ISSUEG((blk + DPGc) * 4);
            cpwait<DPGc - 2>();
            const int t0 = blk * 4;
            SUB0(t0); SUB0(t0 + 1); SUB0(t0 + 2); SUB0(t0 + 3);
        }
        cpwait<0>();
        {
            const int t0 = blk * 4;
            if (rr > 0) SUB0(t0);
            if (rr > 1) SUB0(t0 + 1);
            if (rr > 2) SUB0(t0 + 2);
        }
        if (rem32 && lane == 31) strel(progA, ncfull + 1);
    } else {
        for (int c = 0; c < ncfull; ++c) {
            spinwait(progA, c + 1);
            __syncwarp();
            for (int qq = 0; qq < 8; ++qq, ++blk) {
                ISSUEG((blk + DPGc) * 4);
                cpwait<DPGc - 2>();
                const int t0 = blk * 4;
                SUB1(t0); SUB1(t0 + 1); SUB1(t0 + 2); SUB1(t0 + 3);
            }
        }
        if (rem32) {
            spinwait(progA, ncfull + 1);
            __syncwarp();
            const int rb = rem32 >> 2, rr = rem32 & 3;
            for (int qq = 0; qq < rb; ++qq, ++blk) {
                ISSUEG((blk + DPGc) * 4);
                cpwait<DPGc - 2>();
                const int t0 = blk * 4;
                SUB1(t0); SUB1(t0 + 1); SUB1(t0 + 2); SUB1(t0 + 3);
            }
            cpwait<0>();
            const int t0 = blk * 4;
            if (rr > 0) SUB1(t0);
            if (rr > 1) SUB1(t0 + 1);
            if (rr > 2) SUB1(t0 + 2);
        } else {
            cpwait<0>();
        }
    }
#undef SUB0
#undef SUB1
#undef ISSUEG
#undef LDCONV

    // blank-logp sum C_b (role 0, fixed order -> deterministic)
    float Cacc = 0.0f;
    if (role == 0) {
#pragma unroll
        for (int j = 0; j < 8; ++j) Cacc += g_Cpart[b * 256 + lane * 8 + j];
#pragma unroll
        for (int o2 = 16; o2; o2 >>= 1) Cacc += __shfl_xor_sync(0xffffffffu, Cacc, o2);
    }

    // epilogue: all warps done (and all cp.async drained) before scratch writes
    __syncthreads();
    float* sE = sEOAll + q * 520;
    float* sO = sE + 258;
#pragma unroll
    for (int j = 0; j < 4; ++j) { sE[pbase + j] = E[j]; sO[pbase + j] = O[j]; }
    if (role == 1 && lane == 31) sE[256] = Eex;   // state 512 (E_256)
    __syncthreads();
    if (role == 0 && lane == 0) {
        float vb = sE[Ut];                        // alpha_hat[2*Ut]
        float vl = sO[Ut - 1];                    // alpha_hat[2*Ut - 1]
        g_nll[b] = -(fmaxf(vb, vl) + Cacc);
    }
}

// ---------------------------------------------------------------------------
// Kernel 3: reduce to scalar loss (fixed-order, deterministic)
// ---------------------------------------------------------------------------
__global__ void __launch_bounds__(32) finalize_kernel(const int* __restrict__ loglen,
                                                      float* __restrict__ out) {
    int lane = threadIdx.x;
    float s = 0.0f, c = 0.0f;
    for (int bb = lane; bb < Bb; bb += 32) { s += g_nll[bb]; c += (float)loglen[bb]; }
#pragma unroll
    for (int o = 16; o; o >>= 1) {
        s += __shfl_xor_sync(0xffffffffu, s, o);
        c += __shfl_xor_sync(0xffffffffu, c, o);
    }
    if (lane == 0) out[0] = s / c;
}

// ---------------------------------------------------------------------------
extern "C" void kernel_launch(void* const* d_in, const int* in_sizes, int n_in,
                              void* d_out, int out_size) {
    const float* logits  = (const float*)d_in[0];
    const int*   targets = (const int*)d_in[1];
    const int*   loglen  = (const int*)d_in[2];
    const int*   tgtlen  = (const int*)d_in[3];

    const int dpSmem = 8 * RINGB + (4 * (Tt + 8) + 4 * 520 + 4 * 32 + 8) * (int)sizeof(float);
    cudaFuncSetAttribute(dp_kernel, cudaFuncAttributeMaxDynamicSharedMemorySize, dpSmem);

    gather_kernel<<<dim3(Tt / GB_ROWS, Bb), 256>>>(logits, targets, loglen);
    dp_kernel<<<16, 256, dpSmem>>>(targets, loglen, tgtlen);
    finalize_kernel<<<1, 32>>>(loglen, (float*)d_out);
}

// round 11
// speedup vs baseline: 1.3702x; 1.3702x over previous
#include <cuda_runtime.h>
#include <cuda_fp16.h>
#include <math.h>

#define Bb 64
#define Tt 2048
#define Vv 256
#define Uu 256
#define NEGV (-1e30f)

__device__ __half g_dh[(size_t)Bb * Tt * 256]; // d[b,t,i] = logits[b,t,tgt[i]] - logits[b,t,0]
__device__ float  g_Cpart[Bb * 256];           // per-8-row blank-logp partials
__device__ float  g_nll[Bb];

__device__ __forceinline__ void cp16(unsigned sa, const float* g) {
    asm volatile("cp.async.cg.shared.global [%0], [%1], 16;\n" :: "r"(sa), "l"(g) : "memory");
}
__device__ __forceinline__ void cp8(unsigned sa, const void* g) {
    asm volatile("cp.async.ca.shared.global [%0], [%1], 8;\n" :: "r"(sa), "l"(g) : "memory");
}
__device__ __forceinline__ void cpcommit() {
    asm volatile("cp.async.commit_group;\n" ::: "memory");
}
template<int N> __device__ __forceinline__ void cpwait() {
    asm volatile("cp.async.wait_group %0;\n" :: "n"(N) : "memory");
}
__device__ __forceinline__ void strel(unsigned a, int v) {
    asm volatile("st.release.cta.shared.b32 [%0], %1;" :: "r"(a), "r"(v) : "memory");
}
__device__ __forceinline__ void spinwait(unsigned a, int need) {
    int v;
    do { asm volatile("ld.acquire.cta.shared.b32 %0, [%1];" : "=r"(v) : "r"(a) : "memory"); } while (v < need);
}

// ---------------------------------------------------------------------------
// Kernel 1: fused lse + emission-delta gather (fp16 out) + blank-logp partials.
// (proven in R10: 30.6us)
// ---------------------------------------------------------------------------
#define GB_ROWS 64
__global__ void __launch_bounds__(256) gather_kernel(const float* __restrict__ logits,
                                                     const int*  __restrict__ targets,
                                                     const int*  __restrict__ loglen) {
    __shared__ int   sTgt[Uu];
    __shared__ float sRow[8][4][Vv];

    const int b  = blockIdx.y;
    const int c  = blockIdx.x;
    const int L  = loglen[b];
    const int t0 = c * GB_ROWS;
    if (t0 >= L) return;

    const int tid = threadIdx.x, w = tid >> 5, lane = tid & 31;
    sTgt[tid] = targets[b * Uu + tid];
    __syncthreads();

    const int tbase = t0 + w * 8;
    if (tbase >= L) return;
    int nrows = L - tbase; if (nrows > 8) nrows = 8;

    const float* lg    = logits + ((size_t)b * Tt + tbase) * Vv;
    __half*      dOutH = g_dh   + ((size_t)b * Tt + tbase) * 256;

#pragma unroll
    for (int p = 0; p < 3; ++p) {
        if (p < nrows) {
            unsigned sa = (unsigned)__cvta_generic_to_shared(&sRow[w][p][lane * 8]);
            const float* g = lg + (size_t)p * Vv + lane * 8;
            cp16(sa, g);
            cp16(sa + 16, g + 4);
        }
        cpcommit();
    }

    float cb = 0.0f;
    for (int k = 0; k < nrows; ++k) {
        int pf = k + 3;
        if (pf < nrows) {
            unsigned sa = (unsigned)__cvta_generic_to_shared(&sRow[w][pf & 3][lane * 8]);
            const float* g = lg + (size_t)pf * Vv + lane * 8;
            cp16(sa, g);
            cp16(sa + 16, g + 4);
        }
        cpcommit();
        cpwait<3>();
        __syncwarp();

        const float* r = sRow[w][k & 3];
        float4 v0 = *(const float4*)&r[lane * 4];
        float4 v1 = *(const float4*)&r[128 + lane * 4];
        float s = __expf(v0.x) + __expf(v0.y) + __expf(v0.z) + __expf(v0.w)
                + __expf(v1.x) + __expf(v1.y) + __expf(v1.z) + __expf(v1.w);
#pragma unroll
        for (int o = 16; o; o >>= 1) s += __shfl_xor_sync(0xffffffffu, s, o);
        float lse = __logf(s);
        float r0  = __shfl_sync(0xffffffffu, v0.x, 0);
        cb += r0 - lse;

        int4 tg0 = *(const int4*)&sTgt[lane * 8];
        int4 tg1 = *(const int4*)&sTgt[lane * 8 + 4];
        __half2 a0 = __floats2half2_rn(r[tg0.x] - r0, r[tg0.y] - r0);
        __half2 a1 = __floats2half2_rn(r[tg0.z] - r0, r[tg0.w] - r0);
        __half2 a2 = __floats2half2_rn(r[tg1.x] - r0, r[tg1.y] - r0);
        __half2 a3 = __floats2half2_rn(r[tg1.z] - r0, r[tg1.w] - r0);
        uint4 pk;
        pk.x = *(unsigned*)&a0; pk.y = *(unsigned*)&a1;
        pk.z = *(unsigned*)&a2; pk.w = *(unsigned*)&a3;
        *(uint4*)&dOutH[(size_t)k * 256 + lane * 8] = pk;
        __syncwarp();
    }
    if (lane == 0) g_Cpart[b * 256 + (tbase >> 3)] = cb;
}

// ---------------------------------------------------------------------------
// Kernel 2: Viterbi DP — R9's winning structure (64 blocks x 2 skewed warps)
// with fp16 ring: 128 rows/warp (32 KB), 24 cp.async groups in flight ->
// waited-on group issued ~88 steps earlier (2x R9's lead, half the bytes).
// ---------------------------------------------------------------------------
#define DPGc 24
#define RROWS 128
#define RINGB (RROWS * 256)                  // ring bytes per warp (32 KB)
__global__ void __launch_bounds__(64, 1) dp_kernel(const int* __restrict__ targets,
                                                   const int* __restrict__ loglen,
                                                   const int* __restrict__ tgtlen) {
    extern __shared__ char sm[];
    // layout: rings[2][32KB] | bnd[Tt+8] f32 | sEO[520] f32 | dump[32] f32 | prog
    char*  ringAll = sm;
    float* sBnd    = (float*)(sm + 2 * RINGB);
    float* sEO     = sBnd + (Tt + 8);
    float* sDump   = sEO + 520;
    int*   sProgP  = (int*)(sDump + 32);

    const int tid  = threadIdx.x;
    const int wid  = tid >> 5;
    const int lane = tid & 31;
    const int b    = blockIdx.x;
    const int L    = loglen[b];
    const int Ut   = tgtlen[b];
    const int l4   = lane * 4;
    const int pbase = wid * 128 + l4;            // global pair index base
    const __half* __restrict__ emB = g_dh + (size_t)b * Tt * 256 + wid * 128;
    char* ring = ringAll + wid * RINGB;
    const unsigned ringB2 = (unsigned)__cvta_generic_to_shared(ring);
    const unsigned bndB   = (unsigned)__cvta_generic_to_shared(sBnd);
    const unsigned progA  = (unsigned)__cvta_generic_to_shared(sProgP);

    if (tid == 0) { *sProgP = 0; sBnd[0] = NEGV; }
    __syncthreads();

    float gate[4];
    {
        int prev = (pbase == 0) ? -1 : targets[b * Uu + pbase - 1];
#pragma unroll
        for (int j = 0; j < 4; ++j) {
            int cur = targets[b * Uu + pbase + j];
            gate[j] = (pbase + j >= 1 && cur != prev) ? 0.0f : NEGV;
            prev = cur;
        }
    }

    float E[4], O[4];
#pragma unroll
    for (int j = 0; j < 4; ++j) { E[j] = NEGV; O[j] = NEGV; }
    if (tid == 0) E[0] = 0.0f;                   // alpha_hat seed
    float Eex = NEGV, pO_cur = NEGV;
    const float pOmask = (lane == 0) ? NEGV : 0.0f;

    // branch-free boundary store: lane31 -> bnd slot, others -> private dump
    const unsigned stBase = (lane == 31) ? bndB
                           : (unsigned)__cvta_generic_to_shared(&sDump[lane]);
    const unsigned stStep = (lane == 31) ? 4u : 0u;

#define LDCONV(DST, SLOT)                                                     \
    {                                                                         \
        uint2 v_ = *(const uint2*)(ring + ((SLOT) << 8) + l4 * 2);            \
        float2 f0_ = __half22float2(*(__half2*)&v_.x);                        \
        float2 f1_ = __half22float2(*(__half2*)&v_.y);                        \
        (DST)[0] = f0_.x; (DST)[1] = f0_.y; (DST)[2] = f1_.x; (DST)[3] = f1_.y; \
    }

#define ISSUEG(ROW0)                                                          \
    {                                                                         \
        _Pragma("unroll")                                                     \
        for (int r_ = 0; r_ < 4; ++r_) {                                      \
            int row_ = (ROW0) + r_;                                           \
            if (row_ < L) {                                                   \
                unsigned sa_ = ringB2 + (((unsigned)row_ & (RROWS-1u)) << 8) + (unsigned)l4 * 2u; \
                cp8(sa_, emB + (size_t)row_ * 256 + l4);                      \
            }                                                                 \
        }                                                                     \
        cpcommit();                                                           \
    }

    // prologue: groups 0..23 (rows 0..95; L >= 1024)
#pragma unroll
    for (int g2 = 0; g2 < DPGc; ++g2) ISSUEG(g2 * 4);
    cpwait<DPGc - 2>();                          // rows 0..7 resident

    float buf[4][4];
    LDCONV(buf[0], 0);
    LDCONV(buf[1], 1);

    const int ncfull = L >> 5;
    const int rem32  = L & 31;
    int blk = 0;

#define SUB0(T)                                                               \
    {                                                                         \
        LDCONV(buf[((T) + 2) & 3], (((T) + 2) & (RROWS - 1)));                \
        const float* dv = buf[(T) & 3];                                       \
        float e3 = E[3], o3 = O[3];                                           \
        float O3n = fmaxf(fmaxf(o3, e3), O[2] + gate[3]) + dv[3];             \
        float E3n = fmaxf(e3, O[2]);                                          \
        float nextPO = __shfl_up_sync(0xffffffffu, O3n, 1);                   \
        unsigned dst_ = stBase + (unsigned)((T) + 1) * stStep;                \
        asm volatile("st.shared.b32 [%0], %1;" :: "r"(dst_), "f"(O3n));       \
        float pO = pO_cur;                                                    \
        _Pragma("unroll")                                                     \
        for (int j = 0; j < 3; ++j) {                                         \
            float e = E[j], o = O[j];                                         \
            E[j] = fmaxf(e, pO);                                              \
            O[j] = fmaxf(fmaxf(o, e), pO + gate[j]) + dv[j];                  \
            pO = o;                                                           \
        }                                                                     \
        E[3] = E3n; O[3] = O3n;                                               \
        pO_cur = nextPO + pOmask;                                             \
    }

#define SUB1(T)                                                               \
    {                                                                         \
        LDCONV(buf[((T) + 2) & 3], (((T) + 2) & (RROWS - 1)));                \
        float bn = sBnd[(T) + 1];                                             \
        const float* dv = buf[(T) & 3];                                       \
        float e3 = E[3], o3 = O[3];                                           \
        float O3n = fmaxf(fmaxf(o3, e3), O[2] + gate[3]) + dv[3];             \
        float E3n = fmaxf(e3, O[2]);                                          \
        float nextPO = __shfl_up_sync(0xffffffffu, O3n, 1);                   \
        Eex = fmaxf(Eex, o3);                                                 \
        float pO = pO_cur;                                                    \
        _Pragma("unroll")                                                     \
        for (int j = 0; j < 3; ++j) {                                         \
            float e = E[j], o = O[j];                                         \
            E[j] = fmaxf(e, pO);                                              \
            O[j] = fmaxf(fmaxf(o, e), pO + gate[j]) + dv[j];                  \
            pO = o;                                                           \
        }                                                                     \
        E[3] = E3n; O[3] = O3n;                                               \
        pO_cur = (lane == 0) ? bn : nextPO;                                   \
    }

    if (wid == 0) {
        for (int c = 0; c < ncfull; ++c) {
            for (int q = 0; q < 8; ++q, ++blk) {
                ISSUEG((blk + DPGc) * 4);
                cpwait<DPGc - 2>();
                const int t0 = blk * 4;
                SUB0(t0); SUB0(t0 + 1); SUB0(t0 + 2); SUB0(t0 + 3);
            }
            if (lane == 31) strel(progA, c + 1);
        }
        const int rb = rem32 >> 2, rr = rem32 & 3;
        for (int q = 0; q < rb; ++q, ++blk) {
            ISSUEG((blk + DPGc) * 4);
            cpwait<DPGc - 2>();
            const int t0 = blk * 4;
            SUB0(t0); SUB0(t0 + 1); SUB0(t0 + 2); SUB0(t0 + 3);
        }
        cpwait<0>();
        {
            const int t0 = blk * 4;
            if (rr > 0) SUB0(t0);
            if (rr > 1) SUB0(t0 + 1);
            if (rr > 2) SUB0(t0 + 2);
        }
        if (rem32 && lane == 31) strel(progA, ncfull + 1);
    } else {
        for (int c = 0; c < ncfull; ++c) {
            spinwait(progA, c + 1);
            __syncwarp();
            for (int q = 0; q < 8; ++q, ++blk) {
                ISSUEG((blk + DPGc) * 4);
                cpwait<DPGc - 2>();
                const int t0 = blk * 4;
                SUB1(t0); SUB1(t0 + 1); SUB1(t0 + 2); SUB1(t0 + 3);
            }
        }
        if (rem32) {
            spinwait(progA, ncfull + 1);
            __syncwarp();
            const int rb = rem32 >> 2, rr = rem32 & 3;
            for (int q = 0; q < rb; ++q, ++blk) {
                ISSUEG((blk + DPGc) * 4);
                cpwait<DPGc - 2>();
                const int t0 = blk * 4;
                SUB1(t0); SUB1(t0 + 1); SUB1(t0 + 2); SUB1(t0 + 3);
            }
            cpwait<0>();
            const int t0 = blk * 4;
            if (rr > 0) SUB1(t0);
            if (rr > 1) SUB1(t0 + 1);
            if (rr > 2) SUB1(t0 + 2);
        } else {
            cpwait<0>();
        }
    }
#undef SUB0
#undef SUB1
#undef ISSUEG
#undef LDCONV

    // blank-logp sum C_b (warp 0, fixed order -> deterministic)
    float Cacc = 0.0f;
    if (wid == 0) {
#pragma unroll
        for (int j = 0; j < 8; ++j) Cacc += g_Cpart[b * 256 + lane * 8 + j];
#pragma unroll
        for (int o2 = 16; o2; o2 >>= 1) Cacc += __shfl_xor_sync(0xffffffffu, Cacc, o2);
    }

    // epilogue
    __syncthreads();
    float* sE = sEO;
    float* sO = sEO + 258;
#pragma unroll
    for (int j = 0; j < 4; ++j) { sE[pbase + j] = E[j]; sO[pbase + j] = O[j]; }
    if (tid == 63) sE[256] = Eex;                // state 512 (E_256), warp1 lane31
    __syncthreads();
    if (tid == 0) {
        float vb = sE[Ut];                       // alpha_hat[2*Ut]
        float vl = sO[Ut - 1];                   // alpha_hat[2*Ut - 1]
        g_nll[b] = -(fmaxf(vb, vl) + Cacc);
    }
}

// ---------------------------------------------------------------------------
// Kernel 3: reduce to scalar loss (fixed-order, deterministic)
// ---------------------------------------------------------------------------
__global__ void __launch_bounds__(32) finalize_kernel(const int* __restrict__ loglen,
                                                      float* __restrict__ out) {
    int lane = threadIdx.x;
    float s = 0.0f, c = 0.0f;
    for (int bb = lane; bb < Bb; bb += 32) { s += g_nll[bb]; c += (float)loglen[bb]; }
#pragma unroll
    for (int o = 16; o; o >>= 1) {
        s += __shfl_xor_sync(0xffffffffu, s, o);
        c += __shfl_xor_sync(0xffffffffu, c, o);
    }
    if (lane == 0) out[0] = s / c;
}

// ---------------------------------------------------------------------------
extern "C" void kernel_launch(void* const* d_in, const int* in_sizes, int n_in,
                              void* d_out, int out_size) {
    const float* logits  = (const float*)d_in[0];
    const int*   targets = (const int*)d_in[1];
    const int*   loglen  = (const int*)d_in[2];
    const int*   tgtlen  = (const int*)d_in[3];

    const int dpSmem = 2 * RINGB + ((Tt + 8) + 520 + 32 + 8) * (int)sizeof(float); // ~76 KB
    cudaFuncSetAttribute(dp_kernel, cudaFuncAttributeMaxDynamicSharedMemorySize, dpSmem);

    gather_kernel<<<dim3(Tt / GB_ROWS, Bb), 256>>>(logits, targets, loglen);
    dp_kernel<<<Bb, 64, dpSmem>>>(targets, loglen, tgtlen);
    finalize_kernel<<<1, 32>>>(loglen, (float*)d_out);
}

// round 12
// speedup vs baseline: 1.4071x; 1.0269x over previous
#include <cuda_runtime.h>
#include <cuda_fp16.h>
#include <math.h>

#define Bb 64
#define Tt 2048
#define Vv 256
#define Uu 256
#define NEGV (-1e30f)

__device__ float g_nll[Bb];

__device__ __forceinline__ void cp16(unsigned sa, const float* g) {
    asm volatile("cp.async.cg.shared.global [%0], [%1], 16;\n" :: "r"(sa), "l"(g) : "memory");
}
__device__ __forceinline__ void cpcommit() {
    asm volatile("cp.async.commit_group;\n" ::: "memory");
}
template<int N> __device__ __forceinline__ void cpwait() {
    asm volatile("cp.async.wait_group %0;\n" :: "n"(N) : "memory");
}
__device__ __forceinline__ void strel(unsigned a, int v) {
    asm volatile("st.release.cta.shared.b32 [%0], %1;" :: "r"(a), "r"(v) : "memory");
}
__device__ __forceinline__ int ldacq(unsigned a) {
    int v;
    asm volatile("ld.acquire.cta.shared.b32 %0, [%1];" : "=r"(v) : "r"(a) : "memory");
    return v;
}
__device__ __forceinline__ void spinw(unsigned a, int need) {
    if (ldacq(a) >= need) return;
    do { __nanosleep(32); } while (ldacq(a) < need);
}

// smem layout (bytes from dynamic base)
#define OFF_RING   0            // 128 slots x 512B fp16 d-rows          = 65536
#define OFF_LOG    65536        // 6 warps x 8 slots x 1KB logits stage  = 49152
#define OFF_BND    114688       // (Tt+8) f32                            = 8224
#define OFF_TGT    122912       // 256 int                               = 1024
#define OFF_EO     123936       // 520 f32 (sE[258] | sO[256] packed)    = 2080
#define OFF_DUMP   126016       // 32 f32                                = 128
#define OFF_CB     126144       // 6 f32 (pad 32)                        = 32
#define OFF_PP     126176       // 6 int prod progress (pad 32)          = 32
#define OFF_CP     126208       // cons progress (warp7)                 = 4
#define OFF_DP     126212       // dp progress (warp6)                   = 4
#define SMEM_TOTAL 126464

// ===========================================================================
// Fused kernel: one block per batch.
//  warps 0..5: producers (logits -> lse/cb + fp16 d-rows into smem ring)
//  warp 6:     DP lo (pairs 0..127), publishes boundary + 32-step progress
//  warp 7:     DP hi (pairs 128..255 + state 512), one chunk behind warp 6
// ===========================================================================
__global__ void __launch_bounds__(256, 1) fused_kernel(const float* __restrict__ logits,
                                                       const int*  __restrict__ targets,
                                                       const int*  __restrict__ loglen,
                                                       const int*  __restrict__ tgtlen) {
    extern __shared__ char sm[];
    char*  sRing = sm + OFF_RING;
    float* sLog  = (float*)(sm + OFF_LOG);
    float* sBnd  = (float*)(sm + OFF_BND);
    int*   sTgt  = (int*)(sm + OFF_TGT);
    float* sEO   = (float*)(sm + OFF_EO);
    float* sDump = (float*)(sm + OFF_DUMP);
    float* sCb   = (float*)(sm + OFF_CB);
    const unsigned ppBase = (unsigned)__cvta_generic_to_shared(sm + OFF_PP);
    const unsigned cpAddr = (unsigned)__cvta_generic_to_shared(sm + OFF_CP);
    const unsigned dpAddr = (unsigned)__cvta_generic_to_shared(sm + OFF_DP);

    const int tid  = threadIdx.x;
    const int wid  = tid >> 5;
    const int lane = tid & 31;
    const int b    = blockIdx.x;
    const int L    = loglen[b];
    const int Ut   = tgtlen[b];

    // block init
    sTgt[tid] = targets[b * Uu + tid];
    if (tid < 6) { ((int*)(sm + OFF_PP))[tid] = 0; sCb[tid] = 0.0f; }
    if (tid == 0) { *(int*)(sm + OFF_CP) = 0; *(int*)(sm + OFF_DP) = 0; sBnd[0] = NEGV; }
    __syncthreads();

    if (wid < 6) {
        // ==================================================================
        // PRODUCER warp w: chunks w, w+6, w+12, ... (8 rows each).
        // Two rows per iteration (interleaved lse chains), 8-slot staging.
        // ==================================================================
        const int w = wid;
        const float* lgB = logits + (size_t)b * Tt * Vv;
        float* stage = sLog + w * (8 * 256);
        const unsigned stageB = (unsigned)__cvta_generic_to_shared(stage);
        const unsigned ppA = ppBase + (unsigned)w * 4u;
        const int4 tg0 = *(const int4*)&sTgt[lane * 8];
        const int4 tg1 = *(const int4*)&sTgt[lane * 8 + 4];

#define ROWOF(J) (8 * w + 48 * ((J) >> 3) + ((J) & 7))
        // prologue: prefetch j = 0..5 (one group each)
#pragma unroll
        for (int p = 0; p < 6; ++p) {
            int r = ROWOF(p);
            if (r < L) {
                unsigned sa = stageB + ((unsigned)p << 10) + (unsigned)lane * 32u;
                const float* g = lgB + (size_t)r * Vv + lane * 8;
                cp16(sa, g); cp16(sa + 16, g + 4);
            }
            cpcommit();
        }

        float cb = 0.0f;
        for (int j = 0; ; j += 2) {
            const int rA = ROWOF(j);
            if (rA >= L) break;
            const int rB = rA + 1;            // same chunk ((j&7) even <= 6)
            const bool bval = (rB < L);

            // prefetch j+6, j+7
            {
                int r6 = ROWOF(j + 6);
                if (r6 < L) {
                    unsigned sa = stageB + ((unsigned)((j + 6) & 7) << 10) + (unsigned)lane * 32u;
                    const float* g = lgB + (size_t)r6 * Vv + lane * 8;
                    cp16(sa, g); cp16(sa + 16, g + 4);
                }
                cpcommit();
                int r7 = ROWOF(j + 7);
                if (r7 < L) {
                    unsigned sa = stageB + ((unsigned)((j + 7) & 7) << 10) + (unsigned)lane * 32u;
                    const float* g = lgB + (size_t)r7 * Vv + lane * 8;
                    cp16(sa, g); cp16(sa + 16, g + 4);
                }
                cpcommit();
            }
            cpwait<6>();          // rows j, j+1 staged
            __syncwarp();

            // backpressure: ring slot free when row < 32*consProg + 128
            {
                int rmax = bval ? rB : rA;
                if (rmax >= 128) spinw(cpAddr, (rmax - 96) >> 5);
            }

            const float* ra = stage + (j & 7) * 256;
            const float* rb = stage + ((j + 1) & 7) * 256;
            float4 a0 = *(const float4*)&ra[lane * 4];
            float4 a1 = *(const float4*)&ra[128 + lane * 4];
            float4 b0 = *(const float4*)&rb[lane * 4];
            float4 b1 = *(const float4*)&rb[128 + lane * 4];
            float sa = __expf(a0.x) + __expf(a0.y) + __expf(a0.z) + __expf(a0.w)
                     + __expf(a1.x) + __expf(a1.y) + __expf(a1.z) + __expf(a1.w);
            float sb = __expf(b0.x) + __expf(b0.y) + __expf(b0.z) + __expf(b0.w)
                     + __expf(b1.x) + __expf(b1.y) + __expf(b1.z) + __expf(b1.w);
#pragma unroll
            for (int o = 16; o; o >>= 1) {      // two independent chains overlap
                sa += __shfl_xor_sync(0xffffffffu, sa, o);
                sb += __shfl_xor_sync(0xffffffffu, sb, o);
            }
            float r0a = __shfl_sync(0xffffffffu, a0.x, 0);
            float r0b = __shfl_sync(0xffffffffu, b0.x, 0);
            cb += r0a - __logf(sa);
            if (bval) cb += r0b - __logf(sb);

            // gather d, pack fp16, store to ring
            {
                __half2 h0 = __floats2half2_rn(ra[tg0.x] - r0a, ra[tg0.y] - r0a);
                __half2 h1 = __floats2half2_rn(ra[tg0.z] - r0a, ra[tg0.w] - r0a);
                __half2 h2 = __floats2half2_rn(ra[tg1.x] - r0a, ra[tg1.y] - r0a);
                __half2 h3 = __floats2half2_rn(ra[tg1.z] - r0a, ra[tg1.w] - r0a);
                uint4 pk;
                pk.x = *(unsigned*)&h0; pk.y = *(unsigned*)&h1;
                pk.z = *(unsigned*)&h2; pk.w = *(unsigned*)&h3;
                *(uint4*)(sRing + (((unsigned)rA & 127u) << 9) + (unsigned)lane * 16u) = pk;
            }
            if (bval) {
                __half2 h0 = __floats2half2_rn(rb[tg0.x] - r0b, rb[tg0.y] - r0b);
                __half2 h1 = __floats2half2_rn(rb[tg0.z] - r0b, rb[tg0.w] - r0b);
                __half2 h2 = __floats2half2_rn(rb[tg1.x] - r0b, rb[tg1.y] - r0b);
                __half2 h3 = __floats2half2_rn(rb[tg1.z] - r0b, rb[tg1.w] - r0b);
                uint4 pk;
                pk.x = *(unsigned*)&h0; pk.y = *(unsigned*)&h1;
                pk.z = *(unsigned*)&h2; pk.w = *(unsigned*)&h3;
                *(uint4*)(sRing + (((unsigned)rB & 127u) << 9) + (unsigned)lane * 16u) = pk;
            }

            // release chunk when complete (row 7 of chunk, or last valid row)
            if (((j & 7) == 6) || (ROWOF(j + 2) >= L)) {
                __syncwarp();
                if (lane == 0) strel(ppA, (j >> 3) + 1);
            }
        }
        if (lane == 0) sCb[w] = cb;
#undef ROWOF
    } else {
        // ==================================================================
        // CONSUMER: DP over the ring. role 0 = warp6 (lo), role 1 = warp7 (hi)
        // ==================================================================
        const int role = wid - 6;
        const int l4 = lane * 4;
        const int pbase = role * 128 + l4;
        const unsigned roleOff = (unsigned)role << 8;   // 256 bytes
        const unsigned bndB = (unsigned)__cvta_generic_to_shared(sBnd);

        float gate[4];
        {
            int prev = (pbase == 0) ? -1 : sTgt[pbase - 1];
#pragma unroll
            for (int jj = 0; jj < 4; ++jj) {
                int cur = sTgt[pbase + jj];
                gate[jj] = (pbase + jj >= 1 && cur != prev) ? 0.0f : NEGV;
                prev = cur;
            }
        }
        float E[4], O[4];
#pragma unroll
        for (int jj = 0; jj < 4; ++jj) { E[jj] = NEGV; O[jj] = NEGV; }
        if (pbase == 0) E[0] = 0.0f;
        float Eex = NEGV, pO_cur = NEGV;
        const float pOmask = (lane == 0) ? NEGV : 0.0f;
        const unsigned stBase = (lane == 31) ? bndB
                               : (unsigned)__cvta_generic_to_shared(&sDump[lane]);
        const unsigned stStep = (lane == 31) ? 4u : 0u;

        float buf[4][4];
#define LDCONV(DST, SLOT)                                                     \
        {                                                                     \
            uint2 v_ = *(const uint2*)(sRing + ((unsigned)(SLOT) << 9) + roleOff + ((unsigned)lane << 3)); \
            float2 f0_ = __half22float2(*(__half2*)&v_.x);                    \
            float2 f1_ = __half22float2(*(__half2*)&v_.y);                    \
            (DST)[0] = f0_.x; (DST)[1] = f0_.y; (DST)[2] = f1_.x; (DST)[3] = f1_.y; \
        }
#define WAITCHUNK(C) spinw(ppBase + (unsigned)((C) % 6) * 4u, (C) / 6 + 1)

#define SUB0(T)                                                               \
        {                                                                     \
            LDCONV(buf[((T) + 2) & 3], (((T) + 2) & 127));                    \
            const float* dv = buf[(T) & 3];                                   \
            float e3 = E[3], o3 = O[3];                                       \
            float O3n = fmaxf(fmaxf(o3, e3), O[2] + gate[3]) + dv[3];         \
            float E3n = fmaxf(e3, O[2]);                                      \
            float nextPO = __shfl_up_sync(0xffffffffu, O3n, 1);               \
            unsigned dst_ = stBase + (unsigned)((T) + 1) * stStep;            \
            asm volatile("st.shared.b32 [%0], %1;" :: "r"(dst_), "f"(O3n));   \
            float pO = pO_cur;                                                \
            _Pragma("unroll")                                                 \
            for (int jj = 0; jj < 3; ++jj) {                                  \
                float e = E[jj], o = O[jj];                                   \
                E[jj] = fmaxf(e, pO);                                         \
                O[jj] = fmaxf(fmaxf(o, e), pO + gate[jj]) + dv[jj];           \
                pO = o;                                                       \
            }                                                                 \
            E[3] = E3n; O[3] = O3n;                                           \
            pO_cur = nextPO + pOmask;                                         \
        }

#define SUB1(T)                                                               \
        {                                                                     \
            LDCONV(buf[((T) + 2) & 3], (((T) + 2) & 127));                    \
            float bn = sBnd[(T) + 1];                                         \
            const float* dv = buf[(T) & 3];                                   \
            float e3 = E[3], o3 = O[3];                                       \
            float O3n = fmaxf(fmaxf(o3, e3), O[2] + gate[3]) + dv[3];         \
            float E3n = fmaxf(e3, O[2]);                                      \
            float nextPO = __shfl_up_sync(0xffffffffu, O3n, 1);               \
            Eex = fmaxf(Eex, o3);                                             \
            float pO = pO_cur;                                                \
            _Pragma("unroll")                                                 \
            for (int jj = 0; jj < 3; ++jj) {                                  \
                float e = E[jj], o = O[jj];                                   \
                E[jj] = fmaxf(e, pO);                                         \
                O[jj] = fmaxf(fmaxf(o, e), pO + gate[jj]) + dv[jj];           \
                pO = o;                                                       \
            }                                                                 \
            E[3] = E3n; O[3] = O3n;                                           \
            pO_cur = (lane == 0) ? bn : nextPO;                               \
        }

        const int ncfull = L >> 5;
        const int rem32  = L & 31;
        int t = 0;

        if (role == 0) {
            WAITCHUNK(0); WAITCHUNK(1);
            __syncwarp();
            LDCONV(buf[0], 0); LDCONV(buf[1], 1);
            for (int c = 0; c < ncfull; ++c) {
                for (int q = 0; q < 4; ++q) {
                    int gc = c * 4 + q;
                    if (8 * (gc + 1) < L) { WAITCHUNK(gc + 1); __syncwarp(); }
                    SUB0(t); SUB0(t + 1); SUB0(t + 2); SUB0(t + 3);
                    SUB0(t + 4); SUB0(t + 5); SUB0(t + 6); SUB0(t + 7);
                    t += 8;
                }
                if (lane == 31) strel(dpAddr, c + 1);
            }
            if (rem32) {
                int lastChunk = (L - 1) >> 3;
                for (int cc = 4 * ncfull; cc <= lastChunk; ++cc) WAITCHUNK(cc);
                __syncwarp();
                for (int k = 0; k < rem32; ++k) { SUB0(t); ++t; }
                if (lane == 31) strel(dpAddr, ncfull + 1);
            }
        } else {
            for (int c = 0; c < ncfull; ++c) {
                spinw(dpAddr, c + 1);
                __syncwarp();
                if (c == 0) { LDCONV(buf[0], 0); LDCONV(buf[1], 1); }
                for (int q = 0; q < 4; ++q) {
                    SUB1(t); SUB1(t + 1); SUB1(t + 2); SUB1(t + 3);
                    SUB1(t + 4); SUB1(t + 5); SUB1(t + 6); SUB1(t + 7);
                    t += 8;
                }
                __syncwarp();
                if (lane == 31) strel(cpAddr, c + 1);
            }
            if (rem32) {
                spinw(dpAddr, ncfull + 1);
                __syncwarp();
                for (int k = 0; k < rem32; ++k) { SUB1(t); ++t; }
            }
        }
#undef SUB0
#undef SUB1
#undef WAITCHUNK
#undef LDCONV

        // write alpha halves
        float* sE = sEO;
        float* sO = sEO + 258;
#pragma unroll
        for (int jj = 0; jj < 4; ++jj) { sE[pbase + jj] = E[jj]; sO[pbase + jj] = O[jj]; }
        if (role == 1 && lane == 31) sE[256] = Eex;
    }

    __syncthreads();
    if (wid == 6 && lane == 0) {
        float Cacc = sCb[0] + sCb[1] + sCb[2] + sCb[3] + sCb[4] + sCb[5];
        float vb = sEO[Ut];            // alpha_hat[2*Ut]
        float vl = sEO[258 + Ut - 1];  // alpha_hat[2*Ut - 1]
        g_nll[b] = -(fmaxf(vb, vl) + Cacc);
    }
}

// ---------------------------------------------------------------------------
// Finalize: reduce to scalar loss (fixed-order, deterministic)
// ---------------------------------------------------------------------------
__global__ void __launch_bounds__(32) finalize_kernel(const int* __restrict__ loglen,
                                                      float* __restrict__ out) {
    int lane = threadIdx.x;
    float s = 0.0f, c = 0.0f;
    for (int bb = lane; bb < Bb; bb += 32) { s += g_nll[bb]; c += (float)loglen[bb]; }
#pragma unroll
    for (int o = 16; o; o >>= 1) {
        s += __shfl_xor_sync(0xffffffffu, s, o);
        c += __shfl_xor_sync(0xffffffffu, c, o);
    }
    if (lane == 0) out[0] = s / c;
}

// ---------------------------------------------------------------------------
extern "C" void kernel_launch(void* const* d_in, const int* in_sizes, int n_in,
                              void* d_out, int out_size) {
    const float* logits  = (const float*)d_in[0];
    const int*   targets = (const int*)d_in[1];
    const int*   loglen  = (const int*)d_in[2];
    const int*   tgtlen  = (const int*)d_in[3];

    cudaFuncSetAttribute(fused_kernel, cudaFuncAttributeMaxDynamicSharedMemorySize, SMEM_TOTAL);

    fused_kernel<<<Bb, 256, SMEM_TOTAL>>>(logits, targets, loglen, tgtlen);
    finalize_kernel<<<1, 32>>>(loglen, (float*)d_out);
}